// round 1
// baseline (speedup 1.0000x reference)
#include <cuda_runtime.h>
#include <math.h>
#include <float.h>

// Problem constants
#define B_    2
#define T_    2048
#define DM_   2048
#define H_    16
#define HKV_  4
#define DK_   128
#define GRP_  (H_/HKV_)

// Scratch (static device globals; no allocation allowed)
__device__ float g_Q[(size_t)B_*T_*H_*DK_];     // 32 MB  [B,T,H,DK]
__device__ float g_K[(size_t)B_*T_*HKV_*DK_];   //  8 MB  [B,T,HKV,DK]
__device__ float g_V[(size_t)B_*T_*HKV_*DK_];   //  8 MB
__device__ float g_O[(size_t)B_*T_*H_*DK_];     // 32 MB  [B,T,H,DK]

// ---------------------------------------------------------------------------
// SGEMM: C[m,n] = sum_k A[m,k] * W[n,k]   (A row-major MxK, W row-major NxK)
// 128x128 block tile, K-step 8, 256 threads, 8x8 microtile per thread.
// M,N multiples of 128; K multiple of 8 (true for all our shapes).
// ---------------------------------------------------------------------------
__global__ __launch_bounds__(256) void sgemm_nt(
    const float* __restrict__ A, const float* __restrict__ W,
    float* __restrict__ C, int M, int N, int K)
{
    __shared__ float As[8][128];
    __shared__ float Bs[8][128];

    const int tid  = threadIdx.x;
    const int row0 = blockIdx.y * 128;
    const int col0 = blockIdx.x * 128;

    const int lm = tid >> 1;          // 0..127 : tile row loaded by this thread
    const int lk = (tid & 1) * 4;     // 0 or 4 : k offset (float4)
    const float* Aptr = A + (size_t)(row0 + lm) * K + lk;
    const float* Wptr = W + (size_t)(col0 + lm) * K + lk;

    const int ty = tid >> 4;          // 0..15
    const int tx = tid & 15;          // 0..15

    float acc[8][8];
#pragma unroll
    for (int i = 0; i < 8; i++)
#pragma unroll
        for (int j = 0; j < 8; j++) acc[i][j] = 0.f;

    for (int k0 = 0; k0 < K; k0 += 8) {
        float4 av = *(const float4*)(Aptr + k0);
        float4 bv = *(const float4*)(Wptr + k0);
        __syncthreads();
        As[lk + 0][lm] = av.x; As[lk + 1][lm] = av.y;
        As[lk + 2][lm] = av.z; As[lk + 3][lm] = av.w;
        Bs[lk + 0][lm] = bv.x; Bs[lk + 1][lm] = bv.y;
        Bs[lk + 2][lm] = bv.z; Bs[lk + 3][lm] = bv.w;
        __syncthreads();
#pragma unroll
        for (int k = 0; k < 8; k++) {
            float a[8], b[8];
            *(float4*)(a)     = *(const float4*)&As[k][ty * 8];
            *(float4*)(a + 4) = *(const float4*)&As[k][ty * 8 + 4];
            *(float4*)(b)     = *(const float4*)&Bs[k][tx * 8];
            *(float4*)(b + 4) = *(const float4*)&Bs[k][tx * 8 + 4];
#pragma unroll
            for (int i = 0; i < 8; i++)
#pragma unroll
                for (int j = 0; j < 8; j++)
                    acc[i][j] += a[i] * b[j];
        }
    }

#pragma unroll
    for (int i = 0; i < 8; i++) {
        int r = row0 + ty * 8 + i;
        float4* cp = (float4*)(C + (size_t)r * N + col0 + tx * 8);
        cp[0] = make_float4(acc[i][0], acc[i][1], acc[i][2], acc[i][3]);
        cp[1] = make_float4(acc[i][4], acc[i][5], acc[i][6], acc[i][7]);
    }
}

// ---------------------------------------------------------------------------
// Fused RMSNorm (over head dim) + RoPE (interleaved pairs), in place.
// X layout [B, T, nheads, DK]; one warp per (b,t,h) row, lane owns 4 elems.
// ---------------------------------------------------------------------------
__global__ void rmsnorm_rope(float* __restrict__ X, const float* __restrict__ w,
                             int nheads)
{
    int gwarp = (blockIdx.x * blockDim.x + threadIdx.x) >> 5;
    int lane  = threadIdx.x & 31;
    int total = B_ * T_ * nheads;
    if (gwarp >= total) return;

    int t = (gwarp / nheads) % T_;
    float* row = X + (size_t)gwarp * DK_;

    float4 v = *(float4*)(row + lane * 4);
    float ss = v.x * v.x + v.y * v.y + v.z * v.z + v.w * v.w;
#pragma unroll
    for (int o = 16; o; o >>= 1) ss += __shfl_xor_sync(0xffffffffu, ss, o);

    // eps = finfo(float32).eps
    float scale = rsqrtf(ss * (1.0f / DK_) + 1.1920929e-7f);

    float4 wv = *(const float4*)(w + lane * 4);
    float x0 = v.x * scale * wv.x;
    float x1 = v.y * scale * wv.y;
    float x2 = v.z * scale * wv.z;
    float x3 = v.w * scale * wv.w;

    // RoPE: pairs p0 = lane*2 (elems 4*lane, 4*lane+1), p1 = lane*2+1
    int p0 = lane * 2, p1 = lane * 2 + 1;
    float f0 = powf(10000.0f, -(float)p0 / 64.0f);
    float f1 = powf(10000.0f, -(float)p1 / 64.0f);
    float tf = (float)t;
    float s0, c0, s1, c1;
    sincosf(tf * f0, &s0, &c0);
    sincosf(tf * f1, &s1, &c1);

    float4 out;
    out.x = x0 * c0 - x1 * s0;
    out.y = x1 * c0 + x0 * s0;
    out.z = x2 * c1 - x3 * s1;
    out.w = x3 * c1 + x2 * s1;
    *(float4*)(row + lane * 4) = out;
}

// ---------------------------------------------------------------------------
// FP32 flash attention, causal, GQA.
// Block: 128 threads handles BM=64 query rows for one (b, h, qtile).
// Each query row is owned by a lane pair (lane, lane^16) splitting DK in half.
// K/V tiles (64 x 128 fp32 each) staged in 64 KB dynamic smem.
// Online softmax in 16-key chunks (keeps scores in registers).
// ---------------------------------------------------------------------------
#define BM 64
#define BN 64

__global__ __launch_bounds__(128) void flash_attn()
{
    extern __shared__ float sm[];
    float* Ks = sm;                 // [BN][DK]
    float* Vs = sm + BN * DK_;      // [BN][DK]

    const int qtile = blockIdx.x;
    const int h     = blockIdx.y;
    const int b     = blockIdx.z;
    const int hkv   = h / GRP_;

    const int tid  = threadIdx.x;
    const int lane = tid & 31;
    const int warp = tid >> 5;
    const int r    = warp * 16 + (lane & 15);   // query row within tile
    const int half = lane >> 4;                 // which DK half this thread owns
    const int qt   = qtile * BM + r;            // global query position

    const float* Qrow = g_Q + (((size_t)(b * T_ + qt) * H_ + h) * DK_) + half * 64;
    float q[64];
#pragma unroll
    for (int i = 0; i < 64; i += 4) *(float4*)(q + i) = *(const float4*)(Qrow + i);

    float o[64];
#pragma unroll
    for (int i = 0; i < 64; i++) o[i] = 0.f;
    float m = -1e30f, l = 0.f;
    const float sc = 0.08838834764831845f;   // 1/sqrt(128)

    const int ntiles = qtile + 1;
    for (int kt = 0; kt < ntiles; kt++) {
        __syncthreads();
        const int kbase = kt * BN;
        // stage K and V tiles (coalesced float4 loads)
        for (int idx = tid; idx < BN * (DK_ / 4); idx += 128) {
            int rr = idx >> 5;      // DK/4 == 32
            int c4 = (idx & 31) * 4;
            size_t goff = (((size_t)(b * T_ + kbase + rr) * HKV_ + hkv) * DK_) + c4;
            *(float4*)(Ks + rr * DK_ + c4) = *(const float4*)(g_K + goff);
            *(float4*)(Vs + rr * DK_ + c4) = *(const float4*)(g_V + goff);
        }
        __syncthreads();

        const bool diag = (kt == qtile);
#pragma unroll 1
        for (int c = 0; c < BN; c += 16) {
            float s[16];
#pragma unroll
            for (int j = 0; j < 16; j++) {
                const float* kr = Ks + (c + j) * DK_ + half * 64;
                float acc = 0.f;
#pragma unroll
                for (int i4 = 0; i4 < 16; i4++) {
                    float4 kv = *(const float4*)(kr + i4 * 4);
                    acc += q[i4 * 4 + 0] * kv.x + q[i4 * 4 + 1] * kv.y
                         + q[i4 * 4 + 2] * kv.z + q[i4 * 4 + 3] * kv.w;
                }
                s[j] = acc;
            }
#pragma unroll
            for (int j = 0; j < 16; j++) {
                s[j] += __shfl_xor_sync(0xffffffffu, s[j], 16);
                s[j] *= sc;
                if (diag && (kbase + c + j > qt)) s[j] = -1e30f;
            }
            float mc = m;
#pragma unroll
            for (int j = 0; j < 16; j++) mc = fmaxf(mc, s[j]);
            float corr = __expf(m - mc);
            m = mc;
            float ps = 0.f;
#pragma unroll
            for (int j = 0; j < 16; j++) { s[j] = __expf(s[j] - mc); ps += s[j]; }
            l = l * corr + ps;
#pragma unroll
            for (int i = 0; i < 64; i++) o[i] *= corr;
#pragma unroll
            for (int j = 0; j < 16; j++) {
                const float* vr = Vs + (c + j) * DK_ + half * 64;
                float pj = s[j];
#pragma unroll
                for (int i4 = 0; i4 < 16; i4++) {
                    float4 vv = *(const float4*)(vr + i4 * 4);
                    o[i4 * 4 + 0] += pj * vv.x;
                    o[i4 * 4 + 1] += pj * vv.y;
                    o[i4 * 4 + 2] += pj * vv.z;
                    o[i4 * 4 + 3] += pj * vv.w;
                }
            }
        }
    }

    float inv_l = 1.f / l;
    float* Orow = g_O + (((size_t)(b * T_ + qt) * H_ + h) * DK_) + half * 64;
#pragma unroll
    for (int i = 0; i < 64; i += 4) {
        float4 ov = make_float4(o[i] * inv_l, o[i + 1] * inv_l,
                                o[i + 2] * inv_l, o[i + 3] * inv_l);
        *(float4*)(Orow + i) = ov;
    }
}

// ---------------------------------------------------------------------------
// Launch
// ---------------------------------------------------------------------------
extern "C" void kernel_launch(void* const* d_in, const int* in_sizes, int n_in,
                              void* d_out, int out_size)
{
    const float* x       = (const float*)d_in[0];
    const float* wq      = (const float*)d_in[1];
    const float* wk      = (const float*)d_in[2];
    const float* wv      = (const float*)d_in[3];
    const float* wo      = (const float*)d_in[4];
    const float* q_normw = (const float*)d_in[5];
    const float* k_normw = (const float*)d_in[6];
    float* out = (float*)d_out;

    float *Q, *K, *V, *O;
    cudaGetSymbolAddress((void**)&Q, g_Q);
    cudaGetSymbolAddress((void**)&K, g_K);
    cudaGetSymbolAddress((void**)&V, g_V);
    cudaGetSymbolAddress((void**)&O, g_O);

    const int M = B_ * T_;   // 4096

    // QKV projections
    sgemm_nt<<<dim3(DM_ / 128, M / 128), 256>>>(x, wq, Q, M, H_ * DK_,   DM_);
    sgemm_nt<<<dim3((HKV_ * DK_) / 128, M / 128), 256>>>(x, wk, K, M, HKV_ * DK_, DM_);
    sgemm_nt<<<dim3((HKV_ * DK_) / 128, M / 128), 256>>>(x, wv, V, M, HKV_ * DK_, DM_);

    // RMSNorm + RoPE on Q and K (in place). 4 warps (=rows) per 128-thread block.
    {
        int qrows = B_ * T_ * H_;
        int krows = B_ * T_ * HKV_;
        rmsnorm_rope<<<qrows / 4, 128>>>(Q, q_normw, H_);
        rmsnorm_rope<<<krows / 4, 128>>>(K, k_normw, HKV_);
    }

    // Flash attention
    {
        int smem = 2 * BN * DK_ * (int)sizeof(float);   // 64 KB
        cudaFuncSetAttribute(flash_attn, cudaFuncAttributeMaxDynamicSharedMemorySize, smem);
        flash_attn<<<dim3(T_ / BM, H_, B_), 128, smem>>>();
    }

    // Output projection
    sgemm_nt<<<dim3(DM_ / 128, M / 128), 256>>>(O, wo, out, M, DM_, DM_);
}

// round 3
// speedup vs baseline: 1.5680x; 1.5680x over previous
#include <cuda_runtime.h>
#include <math.h>
#include <float.h>

// Problem constants
#define B_    2
#define T_    2048
#define DM_   2048
#define H_    16
#define HKV_  4
#define DK_   128
#define GRP_  (H_/HKV_)

// Scratch (static device globals; no allocation allowed)
__device__ float g_Q[(size_t)B_*T_*H_*DK_];     // 32 MB  [B,T,H,DK]
__device__ float g_K[(size_t)B_*T_*HKV_*DK_];   //  8 MB  [B,T,HKV,DK]
__device__ float g_V[(size_t)B_*T_*HKV_*DK_];   //  8 MB
__device__ float g_O[(size_t)B_*T_*H_*DK_];     // 32 MB  [B,T,H,DK]

// ---------------------------------------------------------------------------
// TF32 tensor-core GEMM: C[m,n] = sum_k A[m,k] * W[n,k]
// (A row-major MxK, W row-major NxK -> mma row.col with B = W^T col-major)
// 128x128 block tile, BK=16, 256 threads (8 warps), warp tile 64x32,
// m16n8k8 tf32 atoms, fp32 accumulate. M,N multiples of 128; K mult of 16.
// ---------------------------------------------------------------------------
#define GBK 16
#define SPAD 20   // smem row stride in floats (16 + 4 pad): conflict-free frags

__device__ __forceinline__ unsigned f2tf32(float x) {
    unsigned r;
    asm("cvt.rna.tf32.f32 %0, %1;" : "=r"(r) : "f"(x));
    return r;
}

__device__ __forceinline__ void mma_tf32(float* c, const unsigned* a, const unsigned* b) {
    asm volatile(
        "mma.sync.aligned.m16n8k8.row.col.f32.tf32.tf32.f32 "
        "{%0,%1,%2,%3}, {%4,%5,%6,%7}, {%8,%9}, {%0,%1,%2,%3};\n"
        : "+f"(c[0]), "+f"(c[1]), "+f"(c[2]), "+f"(c[3])
        : "r"(a[0]), "r"(a[1]), "r"(a[2]), "r"(a[3]), "r"(b[0]), "r"(b[1]));
}

__global__ __launch_bounds__(256) void gemm_tf32(
    const float* __restrict__ A, const float* __restrict__ W,
    float* __restrict__ C, int M, int N, int K)
{
    __shared__ unsigned As[128 * SPAD];
    __shared__ unsigned Bs[128 * SPAD];

    const int tid  = threadIdx.x;
    const int lane = tid & 31;
    const int warp = tid >> 5;
    const int wm   = warp >> 2;        // 0..1
    const int wn   = warp & 3;         // 0..3
    const int row0 = blockIdx.y * 128;
    const int col0 = blockIdx.x * 128;

    const int lrow = tid >> 1;                 // 0..127
    const int lk   = (tid & 1) * 8;            // 0 or 8
    const float* Ag = A + (size_t)(row0 + lrow) * K + lk;
    const float* Wg = W + (size_t)(col0 + lrow) * K + lk;

    const int g4 = lane >> 2;   // 0..7
    const int q4 = lane & 3;    // 0..3

    float acc[4][4][4];
#pragma unroll
    for (int i = 0; i < 4; i++)
#pragma unroll
        for (int j = 0; j < 4; j++)
#pragma unroll
            for (int r = 0; r < 4; r++) acc[i][j][r] = 0.f;

    // prefetch first tile into registers
    float4 ra0 = *(const float4*)(Ag);
    float4 ra1 = *(const float4*)(Ag + 4);
    float4 rb0 = *(const float4*)(Wg);
    float4 rb1 = *(const float4*)(Wg + 4);

    for (int k0 = 0; k0 < K; k0 += GBK) {
        // store current tile (convert to tf32)
        unsigned* ap = As + lrow * SPAD + lk;
        ap[0] = f2tf32(ra0.x); ap[1] = f2tf32(ra0.y);
        ap[2] = f2tf32(ra0.z); ap[3] = f2tf32(ra0.w);
        ap[4] = f2tf32(ra1.x); ap[5] = f2tf32(ra1.y);
        ap[6] = f2tf32(ra1.z); ap[7] = f2tf32(ra1.w);
        unsigned* bp = Bs + lrow * SPAD + lk;
        bp[0] = f2tf32(rb0.x); bp[1] = f2tf32(rb0.y);
        bp[2] = f2tf32(rb0.z); bp[3] = f2tf32(rb0.w);
        bp[4] = f2tf32(rb1.x); bp[5] = f2tf32(rb1.y);
        bp[6] = f2tf32(rb1.z); bp[7] = f2tf32(rb1.w);
        __syncthreads();

        // prefetch next tile
        if (k0 + GBK < K) {
            ra0 = *(const float4*)(Ag + k0 + GBK);
            ra1 = *(const float4*)(Ag + k0 + GBK + 4);
            rb0 = *(const float4*)(Wg + k0 + GBK);
            rb1 = *(const float4*)(Wg + k0 + GBK + 4);
        }

#pragma unroll
        for (int kk = 0; kk < 2; kk++) {
            const int kb = kk * 8;
            unsigned af[4][4];
#pragma unroll
            for (int ma = 0; ma < 4; ma++) {
                int r = wm * 64 + ma * 16 + g4;
                af[ma][0] = As[(r    ) * SPAD + kb + q4];
                af[ma][1] = As[(r + 8) * SPAD + kb + q4];
                af[ma][2] = As[(r    ) * SPAD + kb + 4 + q4];
                af[ma][3] = As[(r + 8) * SPAD + kb + 4 + q4];
            }
            unsigned bf[4][2];
#pragma unroll
            for (int na = 0; na < 4; na++) {
                int c = wn * 32 + na * 8 + g4;
                bf[na][0] = Bs[c * SPAD + kb + q4];
                bf[na][1] = Bs[c * SPAD + kb + 4 + q4];
            }
#pragma unroll
            for (int ma = 0; ma < 4; ma++)
#pragma unroll
                for (int na = 0; na < 4; na++)
                    mma_tf32(acc[ma][na], af[ma], bf[na]);
        }
        __syncthreads();
    }

    // epilogue: c0,c1 at (row, 2*q4), c2,c3 at (row+8, 2*q4)
#pragma unroll
    for (int ma = 0; ma < 4; ma++) {
#pragma unroll
        for (int na = 0; na < 4; na++) {
            int r = row0 + wm * 64 + ma * 16 + g4;
            int c = col0 + wn * 32 + na * 8 + 2 * q4;
            *(float2*)(C + (size_t)r * N + c) =
                make_float2(acc[ma][na][0], acc[ma][na][1]);
            *(float2*)(C + (size_t)(r + 8) * N + c) =
                make_float2(acc[ma][na][2], acc[ma][na][3]);
        }
    }
}

// ---------------------------------------------------------------------------
// Fused RMSNorm (over head dim) + RoPE (interleaved pairs), in place.
// X layout [B, T, nheads, DK]; one warp per (b,t,h) row, lane owns 4 elems.
// ---------------------------------------------------------------------------
__global__ void rmsnorm_rope(float* __restrict__ X, const float* __restrict__ w,
                             int nheads)
{
    int gwarp = (blockIdx.x * blockDim.x + threadIdx.x) >> 5;
    int lane  = threadIdx.x & 31;
    int total = B_ * T_ * nheads;
    if (gwarp >= total) return;

    int t = (gwarp / nheads) % T_;
    float* row = X + (size_t)gwarp * DK_;

    float4 v = *(float4*)(row + lane * 4);
    float ss = v.x * v.x + v.y * v.y + v.z * v.z + v.w * v.w;
#pragma unroll
    for (int o = 16; o; o >>= 1) ss += __shfl_xor_sync(0xffffffffu, ss, o);

    // eps = finfo(float32).eps
    float scale = rsqrtf(ss * (1.0f / DK_) + 1.1920929e-7f);

    float4 wv = *(const float4*)(w + lane * 4);
    float x0 = v.x * scale * wv.x;
    float x1 = v.y * scale * wv.y;
    float x2 = v.z * scale * wv.z;
    float x3 = v.w * scale * wv.w;

    // RoPE: pairs p0 = lane*2 (elems 4*lane, 4*lane+1), p1 = lane*2+1
    int p0 = lane * 2, p1 = lane * 2 + 1;
    float f0 = powf(10000.0f, -(float)p0 / 64.0f);
    float f1 = powf(10000.0f, -(float)p1 / 64.0f);
    float tf = (float)t;
    float s0, c0, s1, c1;
    sincosf(tf * f0, &s0, &c0);
    sincosf(tf * f1, &s1, &c1);

    float4 out;
    out.x = x0 * c0 - x1 * s0;
    out.y = x1 * c0 + x0 * s0;
    out.z = x2 * c1 - x3 * s1;
    out.w = x3 * c1 + x2 * s1;
    *(float4*)(row + lane * 4) = out;
}

// ---------------------------------------------------------------------------
// FP32 flash attention, causal, GQA.
// Block: 128 threads handles BM=64 query rows for one (b, h, qtile).
// Each query row is owned by a lane pair (lane, lane^16) splitting DK in half.
// K/V tiles (64 x 128 fp32 each) staged in 64 KB dynamic smem.
// Online softmax in 16-key chunks (keeps scores in registers).
// ---------------------------------------------------------------------------
#define BM 64
#define BN 64

__global__ __launch_bounds__(128) void flash_attn()
{
    extern __shared__ float sm[];
    float* Ks = sm;                 // [BN][DK]
    float* Vs = sm + BN * DK_;      // [BN][DK]

    const int qtile = blockIdx.x;
    const int h     = blockIdx.y;
    const int b     = blockIdx.z;
    const int hkv   = h / GRP_;

    const int tid  = threadIdx.x;
    const int lane = tid & 31;
    const int warp = tid >> 5;
    const int r    = warp * 16 + (lane & 15);   // query row within tile
    const int half = lane >> 4;                 // which DK half this thread owns
    const int qt   = qtile * BM + r;            // global query position

    const float* Qrow = g_Q + (((size_t)(b * T_ + qt) * H_ + h) * DK_) + half * 64;
    float q[64];
#pragma unroll
    for (int i = 0; i < 64; i += 4) *(float4*)(q + i) = *(const float4*)(Qrow + i);

    float o[64];
#pragma unroll
    for (int i = 0; i < 64; i++) o[i] = 0.f;
    float m = -1e30f, l = 0.f;
    const float sc = 0.08838834764831845f;   // 1/sqrt(128)

    const int ntiles = qtile + 1;
    for (int kt = 0; kt < ntiles; kt++) {
        __syncthreads();
        const int kbase = kt * BN;
        for (int idx = tid; idx < BN * (DK_ / 4); idx += 128) {
            int rr = idx >> 5;      // DK/4 == 32
            int c4 = (idx & 31) * 4;
            size_t goff = (((size_t)(b * T_ + kbase + rr) * HKV_ + hkv) * DK_) + c4;
            *(float4*)(Ks + rr * DK_ + c4) = *(const float4*)(g_K + goff);
            *(float4*)(Vs + rr * DK_ + c4) = *(const float4*)(g_V + goff);
        }
        __syncthreads();

        const bool diag = (kt == qtile);
#pragma unroll 1
        for (int c = 0; c < BN; c += 16) {
            float s[16];
#pragma unroll
            for (int j = 0; j < 16; j++) {
                const float* kr = Ks + (c + j) * DK_ + half * 64;
                float acc = 0.f;
#pragma unroll
                for (int i4 = 0; i4 < 16; i4++) {
                    float4 kv = *(const float4*)(kr + i4 * 4);
                    acc += q[i4 * 4 + 0] * kv.x + q[i4 * 4 + 1] * kv.y
                         + q[i4 * 4 + 2] * kv.z + q[i4 * 4 + 3] * kv.w;
                }
                s[j] = acc;
            }
#pragma unroll
            for (int j = 0; j < 16; j++) {
                s[j] += __shfl_xor_sync(0xffffffffu, s[j], 16);
                s[j] *= sc;
                if (diag && (kbase + c + j > qt)) s[j] = -1e30f;
            }
            float mc = m;
#pragma unroll
            for (int j = 0; j < 16; j++) mc = fmaxf(mc, s[j]);
            float corr = __expf(m - mc);
            m = mc;
            float ps = 0.f;
#pragma unroll
            for (int j = 0; j < 16; j++) { s[j] = __expf(s[j] - mc); ps += s[j]; }
            l = l * corr + ps;
#pragma unroll
            for (int i = 0; i < 64; i++) o[i] *= corr;
#pragma unroll
            for (int j = 0; j < 16; j++) {
                const float* vr = Vs + (c + j) * DK_ + half * 64;
                float pj = s[j];
#pragma unroll
                for (int i4 = 0; i4 < 16; i4++) {
                    float4 vv = *(const float4*)(vr + i4 * 4);
                    o[i4 * 4 + 0] += pj * vv.x;
                    o[i4 * 4 + 1] += pj * vv.y;
                    o[i4 * 4 + 2] += pj * vv.z;
                    o[i4 * 4 + 3] += pj * vv.w;
                }
            }
        }
    }

    float inv_l = 1.f / l;
    float* Orow = g_O + (((size_t)(b * T_ + qt) * H_ + h) * DK_) + half * 64;
#pragma unroll
    for (int i = 0; i < 64; i += 4) {
        float4 ov = make_float4(o[i] * inv_l, o[i + 1] * inv_l,
                                o[i + 2] * inv_l, o[i + 3] * inv_l);
        *(float4*)(Orow + i) = ov;
    }
}

// ---------------------------------------------------------------------------
// Launch
// ---------------------------------------------------------------------------
extern "C" void kernel_launch(void* const* d_in, const int* in_sizes, int n_in,
                              void* d_out, int out_size)
{
    const float* x       = (const float*)d_in[0];
    const float* wq      = (const float*)d_in[1];
    const float* wk      = (const float*)d_in[2];
    const float* wv      = (const float*)d_in[3];
    const float* wo      = (const float*)d_in[4];
    const float* q_normw = (const float*)d_in[5];
    const float* k_normw = (const float*)d_in[6];
    float* out = (float*)d_out;

    float *Q, *K, *V, *O;
    cudaGetSymbolAddress((void**)&Q, g_Q);
    cudaGetSymbolAddress((void**)&K, g_K);
    cudaGetSymbolAddress((void**)&V, g_V);
    cudaGetSymbolAddress((void**)&O, g_O);

    const int M = B_ * T_;   // 4096

    // QKV projections (tf32 tensor cores)
    gemm_tf32<<<dim3(DM_ / 128, M / 128), 256>>>(x, wq, Q, M, H_ * DK_,   DM_);
    gemm_tf32<<<dim3((HKV_ * DK_) / 128, M / 128), 256>>>(x, wk, K, M, HKV_ * DK_, DM_);
    gemm_tf32<<<dim3((HKV_ * DK_) / 128, M / 128), 256>>>(x, wv, V, M, HKV_ * DK_, DM_);

    // RMSNorm + RoPE on Q and K (in place). 4 warps (=rows) per 128-thread block.
    {
        int qrows = B_ * T_ * H_;
        int krows = B_ * T_ * HKV_;
        rmsnorm_rope<<<qrows / 4, 128>>>(Q, q_normw, H_);
        rmsnorm_rope<<<krows / 4, 128>>>(K, k_normw, HKV_);
    }

    // Flash attention
    {
        int smem = 2 * BN * DK_ * (int)sizeof(float);   // 64 KB
        cudaFuncSetAttribute(flash_attn, cudaFuncAttributeMaxDynamicSharedMemorySize, smem);
        flash_attn<<<dim3(T_ / BM, H_, B_), 128, smem>>>();
    }

    // Output projection (tf32 tensor cores)
    gemm_tf32<<<dim3(DM_ / 128, M / 128), 256>>>(O, wo, out, M, DM_, DM_);
}

// round 4
// speedup vs baseline: 2.7503x; 1.7540x over previous
#include <cuda_runtime.h>
#include <math.h>
#include <float.h>

// Problem constants
#define B_    2
#define T_    2048
#define DM_   2048
#define H_    16
#define HKV_  4
#define DK_   128
#define GRP_  (H_/HKV_)

// Scratch (static device globals; no allocation allowed)
__device__ float g_Q[(size_t)B_*T_*H_*DK_];     // 32 MB  [B,T,H,DK]
__device__ float g_K[(size_t)B_*T_*HKV_*DK_];   //  8 MB  [B,T,HKV,DK]
__device__ float g_V[(size_t)B_*T_*HKV_*DK_];   //  8 MB
__device__ float g_O[(size_t)B_*T_*H_*DK_];     // 32 MB  [B,T,H,DK]

__device__ __forceinline__ unsigned f2tf32(float x) {
    unsigned r;
    asm("cvt.rna.tf32.f32 %0, %1;" : "=r"(r) : "f"(x));
    return r;
}

__device__ __forceinline__ void mma_tf32(float* c, const unsigned* a, const unsigned* b) {
    asm volatile(
        "mma.sync.aligned.m16n8k8.row.col.f32.tf32.tf32.f32 "
        "{%0,%1,%2,%3}, {%4,%5,%6,%7}, {%8,%9}, {%0,%1,%2,%3};\n"
        : "+f"(c[0]), "+f"(c[1]), "+f"(c[2]), "+f"(c[3])
        : "r"(a[0]), "r"(a[1]), "r"(a[2]), "r"(a[3]), "r"(b[0]), "r"(b[1]));
}

// ---------------------------------------------------------------------------
// TF32 tensor-core GEMM: C[m,n] = sum_k A[m,k] * W[n,k]   (unchanged, working)
// ---------------------------------------------------------------------------
#define GBK 16
#define SPAD 20

__global__ __launch_bounds__(256) void gemm_tf32(
    const float* __restrict__ A, const float* __restrict__ W,
    float* __restrict__ C, int M, int N, int K)
{
    __shared__ unsigned As[128 * SPAD];
    __shared__ unsigned Bs[128 * SPAD];

    const int tid  = threadIdx.x;
    const int lane = tid & 31;
    const int warp = tid >> 5;
    const int wm   = warp >> 2;
    const int wn   = warp & 3;
    const int row0 = blockIdx.y * 128;
    const int col0 = blockIdx.x * 128;

    const int lrow = tid >> 1;
    const int lk   = (tid & 1) * 8;
    const float* Ag = A + (size_t)(row0 + lrow) * K + lk;
    const float* Wg = W + (size_t)(col0 + lrow) * K + lk;

    const int g4 = lane >> 2;
    const int q4 = lane & 3;

    float acc[4][4][4];
#pragma unroll
    for (int i = 0; i < 4; i++)
#pragma unroll
        for (int j = 0; j < 4; j++)
#pragma unroll
            for (int r = 0; r < 4; r++) acc[i][j][r] = 0.f;

    float4 ra0 = *(const float4*)(Ag);
    float4 ra1 = *(const float4*)(Ag + 4);
    float4 rb0 = *(const float4*)(Wg);
    float4 rb1 = *(const float4*)(Wg + 4);

    for (int k0 = 0; k0 < K; k0 += GBK) {
        unsigned* ap = As + lrow * SPAD + lk;
        ap[0] = f2tf32(ra0.x); ap[1] = f2tf32(ra0.y);
        ap[2] = f2tf32(ra0.z); ap[3] = f2tf32(ra0.w);
        ap[4] = f2tf32(ra1.x); ap[5] = f2tf32(ra1.y);
        ap[6] = f2tf32(ra1.z); ap[7] = f2tf32(ra1.w);
        unsigned* bp = Bs + lrow * SPAD + lk;
        bp[0] = f2tf32(rb0.x); bp[1] = f2tf32(rb0.y);
        bp[2] = f2tf32(rb0.z); bp[3] = f2tf32(rb0.w);
        bp[4] = f2tf32(rb1.x); bp[5] = f2tf32(rb1.y);
        bp[6] = f2tf32(rb1.z); bp[7] = f2tf32(rb1.w);
        __syncthreads();

        if (k0 + GBK < K) {
            ra0 = *(const float4*)(Ag + k0 + GBK);
            ra1 = *(const float4*)(Ag + k0 + GBK + 4);
            rb0 = *(const float4*)(Wg + k0 + GBK);
            rb1 = *(const float4*)(Wg + k0 + GBK + 4);
        }

#pragma unroll
        for (int kk = 0; kk < 2; kk++) {
            const int kb = kk * 8;
            unsigned af[4][4];
#pragma unroll
            for (int ma = 0; ma < 4; ma++) {
                int r = wm * 64 + ma * 16 + g4;
                af[ma][0] = As[(r    ) * SPAD + kb + q4];
                af[ma][1] = As[(r + 8) * SPAD + kb + q4];
                af[ma][2] = As[(r    ) * SPAD + kb + 4 + q4];
                af[ma][3] = As[(r + 8) * SPAD + kb + 4 + q4];
            }
            unsigned bf[4][2];
#pragma unroll
            for (int na = 0; na < 4; na++) {
                int c = wn * 32 + na * 8 + g4;
                bf[na][0] = Bs[c * SPAD + kb + q4];
                bf[na][1] = Bs[c * SPAD + kb + 4 + q4];
            }
#pragma unroll
            for (int ma = 0; ma < 4; ma++)
#pragma unroll
                for (int na = 0; na < 4; na++)
                    mma_tf32(acc[ma][na], af[ma], bf[na]);
        }
        __syncthreads();
    }

#pragma unroll
    for (int ma = 0; ma < 4; ma++) {
#pragma unroll
        for (int na = 0; na < 4; na++) {
            int r = row0 + wm * 64 + ma * 16 + g4;
            int c = col0 + wn * 32 + na * 8 + 2 * q4;
            *(float2*)(C + (size_t)r * N + c) =
                make_float2(acc[ma][na][0], acc[ma][na][1]);
            *(float2*)(C + (size_t)(r + 8) * N + c) =
                make_float2(acc[ma][na][2], acc[ma][na][3]);
        }
    }
}

// ---------------------------------------------------------------------------
// Fused RMSNorm + RoPE (unchanged)
// ---------------------------------------------------------------------------
__global__ void rmsnorm_rope(float* __restrict__ X, const float* __restrict__ w,
                             int nheads)
{
    int gwarp = (blockIdx.x * blockDim.x + threadIdx.x) >> 5;
    int lane  = threadIdx.x & 31;
    int total = B_ * T_ * nheads;
    if (gwarp >= total) return;

    int t = (gwarp / nheads) % T_;
    float* row = X + (size_t)gwarp * DK_;

    float4 v = *(float4*)(row + lane * 4);
    float ss = v.x * v.x + v.y * v.y + v.z * v.z + v.w * v.w;
#pragma unroll
    for (int o = 16; o; o >>= 1) ss += __shfl_xor_sync(0xffffffffu, ss, o);

    float scale = rsqrtf(ss * (1.0f / DK_) + 1.1920929e-7f);

    float4 wv = *(const float4*)(w + lane * 4);
    float x0 = v.x * scale * wv.x;
    float x1 = v.y * scale * wv.y;
    float x2 = v.z * scale * wv.z;
    float x3 = v.w * scale * wv.w;

    int p0 = lane * 2, p1 = lane * 2 + 1;
    float f0 = powf(10000.0f, -(float)p0 / 64.0f);
    float f1 = powf(10000.0f, -(float)p1 / 64.0f);
    float tf = (float)t;
    float s0, c0, s1, c1;
    sincosf(tf * f0, &s0, &c0);
    sincosf(tf * f1, &s1, &c1);

    float4 out;
    out.x = x0 * c0 - x1 * s0;
    out.y = x1 * c0 + x0 * s0;
    out.z = x2 * c1 - x3 * s1;
    out.w = x3 * c1 + x2 * s1;
    *(float4*)(row + lane * 4) = out;
}

// ---------------------------------------------------------------------------
// TF32 tensor-core flash attention, causal, GQA.
// BM=128 queries/block, 8 warps each owning 16 full rows; BN=64 key chunk.
// K/V staged in smem as tf32 (stride 132); P routed via per-warp smem tile.
// Online softmax fp32, warp-local (no cross-warp reductions).
// ---------------------------------------------------------------------------
#define FBM 128
#define FBN 64
#define KVS 132            // padded row stride for K/V/Q tiles (floats)
#define PST 68             // padded row stride for P tile

// smem (in unsigned words):
//  [0, 64*KVS)              : K tile   (prologue: Q rows 0..63)
//  [64*KVS, 128*KVS)        : V tile   (prologue: Q rows 64..127)
//  [128*KVS, +8*16*PST)     : per-warp P tiles
#define SM_PV   (64 * KVS)
#define SM_P    (128 * KVS)
#define SM_WORDS (SM_P + 8 * 16 * PST)

__global__ __launch_bounds__(256, 1) void flash_attn_tc()
{
    extern __shared__ unsigned smu[];

    const int qtile = (gridDim.x - 1) - blockIdx.x;   // heavy tiles first
    const int h     = blockIdx.y;
    const int b     = blockIdx.z;
    const int hkv   = h / GRP_;

    const int tid  = threadIdx.x;
    const int lane = tid & 31;
    const int warp = tid >> 5;
    const int g4   = lane >> 2;
    const int q4   = lane & 3;

    const int qrow0 = qtile * FBM;
    const int rA    = qrow0 + warp * 16 + g4;   // this thread's first row
    const int rB    = rA + 8;                   // second row
    const int wrmax = qrow0 + warp * 16 + 15;   // last row of this warp

    unsigned* Ks = smu;
    unsigned* Vs = smu + SM_PV;
    unsigned* Ps = smu + SM_P + warp * (16 * PST);

    // ---- prologue: stage Q tile (128 x 128) as tf32, grab a-fragments ----
    for (int idx = tid; idx < FBM * (DK_ / 4); idx += 256) {
        int r  = idx >> 5;
        int c4 = (idx & 31) * 4;
        const float4 qv = *(const float4*)(g_Q +
            (((size_t)(b * T_ + qrow0 + r) * H_ + h) * DK_) + c4);
        *(uint4*)(smu + r * KVS + c4) =
            make_uint4(f2tf32(qv.x), f2tf32(qv.y), f2tf32(qv.z), f2tf32(qv.w));
    }
    __syncthreads();

    unsigned qf[16][4];
#pragma unroll
    for (int kat = 0; kat < 16; kat++) {
        int kb = kat * 8;
        int r0 = warp * 16 + g4;
        qf[kat][0] = smu[(r0    ) * KVS + kb + q4];
        qf[kat][1] = smu[(r0 + 8) * KVS + kb + q4];
        qf[kat][2] = smu[(r0    ) * KVS + kb + 4 + q4];
        qf[kat][3] = smu[(r0 + 8) * KVS + kb + 4 + q4];
    }
    __syncthreads();

    float oacc[16][4];
#pragma unroll
    for (int i = 0; i < 16; i++)
#pragma unroll
        for (int j = 0; j < 4; j++) oacc[i][j] = 0.f;
    float m0 = -1e30f, m1 = -1e30f, l0 = 0.f, l1 = 0.f;
    const float sc = 0.08838834764831845f;   // 1/sqrt(128)

    const int nchunks = (qtile + 1) * (FBM / FBN);

    for (int kt = 0; kt < nchunks; kt++) {
        const int kbase = kt * FBN;

        // stage K & V chunk (tf32)
        for (int idx = tid; idx < FBN * (DK_ / 4); idx += 256) {
            int r  = idx >> 5;
            int c4 = (idx & 31) * 4;
            size_t goff = (((size_t)(b * T_ + kbase + r) * HKV_ + hkv) * DK_) + c4;
            const float4 kv = *(const float4*)(g_K + goff);
            const float4 vv = *(const float4*)(g_V + goff);
            *(uint4*)(Ks + r * KVS + c4) =
                make_uint4(f2tf32(kv.x), f2tf32(kv.y), f2tf32(kv.z), f2tf32(kv.w));
            *(uint4*)(Vs + r * KVS + c4) =
                make_uint4(f2tf32(vv.x), f2tf32(vv.y), f2tf32(vv.z), f2tf32(vv.w));
        }
        __syncthreads();

        if (kbase <= wrmax) {    // chunk not fully masked for this warp
            // ---- S = Q K^T (16 x 64) ----
            float sacc[8][4];
#pragma unroll
            for (int n = 0; n < 8; n++)
#pragma unroll
                for (int j = 0; j < 4; j++) sacc[n][j] = 0.f;

#pragma unroll
            for (int kat = 0; kat < 16; kat++) {
                int kb = kat * 8;
#pragma unroll
                for (int nat = 0; nat < 8; nat++) {
                    unsigned bb[2];
                    bb[0] = Ks[(nat * 8 + g4) * KVS + kb + q4];
                    bb[1] = Ks[(nat * 8 + g4) * KVS + kb + 4 + q4];
                    mma_tf32(sacc[nat], qf[kat], bb);
                }
            }

            // ---- scale + causal mask ----
            const bool needmask = (kbase + FBN - 1 > rA);
#pragma unroll
            for (int nat = 0; nat < 8; nat++) {
                int c0 = kbase + nat * 8 + 2 * q4;
                sacc[nat][0] *= sc; sacc[nat][1] *= sc;
                sacc[nat][2] *= sc; sacc[nat][3] *= sc;
                if (needmask) {
                    if (c0     > rA) sacc[nat][0] = -1e30f;
                    if (c0 + 1 > rA) sacc[nat][1] = -1e30f;
                    if (c0     > rB) sacc[nat][2] = -1e30f;
                    if (c0 + 1 > rB) sacc[nat][3] = -1e30f;
                }
            }

            // ---- online softmax (warp-local rows) ----
            float mA = -1e30f, mB = -1e30f;
#pragma unroll
            for (int nat = 0; nat < 8; nat++) {
                mA = fmaxf(mA, fmaxf(sacc[nat][0], sacc[nat][1]));
                mB = fmaxf(mB, fmaxf(sacc[nat][2], sacc[nat][3]));
            }
            mA = fmaxf(mA, __shfl_xor_sync(0xffffffffu, mA, 1));
            mA = fmaxf(mA, __shfl_xor_sync(0xffffffffu, mA, 2));
            mB = fmaxf(mB, __shfl_xor_sync(0xffffffffu, mB, 1));
            mB = fmaxf(mB, __shfl_xor_sync(0xffffffffu, mB, 2));

            float nm0 = fmaxf(m0, mA), nm1 = fmaxf(m1, mB);
            float corr0 = __expf(m0 - nm0);
            float corr1 = __expf(m1 - nm1);
            float ps0 = 0.f, ps1 = 0.f;
#pragma unroll
            for (int nat = 0; nat < 8; nat++) {
                sacc[nat][0] = __expf(sacc[nat][0] - nm0);
                sacc[nat][1] = __expf(sacc[nat][1] - nm0);
                sacc[nat][2] = __expf(sacc[nat][2] - nm1);
                sacc[nat][3] = __expf(sacc[nat][3] - nm1);
                ps0 += sacc[nat][0] + sacc[nat][1];
                ps1 += sacc[nat][2] + sacc[nat][3];
            }
            ps0 += __shfl_xor_sync(0xffffffffu, ps0, 1);
            ps0 += __shfl_xor_sync(0xffffffffu, ps0, 2);
            ps1 += __shfl_xor_sync(0xffffffffu, ps1, 1);
            ps1 += __shfl_xor_sync(0xffffffffu, ps1, 2);
            l0 = l0 * corr0 + ps0;
            l1 = l1 * corr1 + ps1;
            m0 = nm0; m1 = nm1;

#pragma unroll
            for (int nv = 0; nv < 16; nv++) {
                oacc[nv][0] *= corr0; oacc[nv][1] *= corr0;
                oacc[nv][2] *= corr1; oacc[nv][3] *= corr1;
            }

            // ---- stash P (tf32) into per-warp smem tile ----
#pragma unroll
            for (int nat = 0; nat < 8; nat++) {
                int cc = nat * 8 + 2 * q4;
                *(uint2*)(Ps + g4 * PST + cc) =
                    make_uint2(f2tf32(sacc[nat][0]), f2tf32(sacc[nat][1]));
                *(uint2*)(Ps + (g4 + 8) * PST + cc) =
                    make_uint2(f2tf32(sacc[nat][2]), f2tf32(sacc[nat][3]));
            }
            __syncwarp();

            // ---- O += P V  (16 x 128) ----
#pragma unroll
            for (int kat = 0; kat < 8; kat++) {
                int kb = kat * 8;
                unsigned af[4];
                af[0] = Ps[(g4    ) * PST + kb + q4];
                af[1] = Ps[(g4 + 8) * PST + kb + q4];
                af[2] = Ps[(g4    ) * PST + kb + 4 + q4];
                af[3] = Ps[(g4 + 8) * PST + kb + 4 + q4];
#pragma unroll
                for (int nv = 0; nv < 16; nv++) {
                    unsigned bb[2];
                    bb[0] = Vs[(kb + q4    ) * KVS + nv * 8 + g4];
                    bb[1] = Vs[(kb + q4 + 4) * KVS + nv * 8 + g4];
                    mma_tf32(oacc[nv], af, bb);
                }
            }
            __syncwarp();
        }
        __syncthreads();
    }

    // ---- epilogue ----
    float inv0 = 1.f / l0, inv1 = 1.f / l1;
    float* OA = g_O + (((size_t)(b * T_ + rA) * H_ + h) * DK_);
    float* OB = g_O + (((size_t)(b * T_ + rB) * H_ + h) * DK_);
#pragma unroll
    for (int nv = 0; nv < 16; nv++) {
        int cc = nv * 8 + 2 * q4;
        *(float2*)(OA + cc) = make_float2(oacc[nv][0] * inv0, oacc[nv][1] * inv0);
        *(float2*)(OB + cc) = make_float2(oacc[nv][2] * inv1, oacc[nv][3] * inv1);
    }
}

// ---------------------------------------------------------------------------
// Launch
// ---------------------------------------------------------------------------
extern "C" void kernel_launch(void* const* d_in, const int* in_sizes, int n_in,
                              void* d_out, int out_size)
{
    const float* x       = (const float*)d_in[0];
    const float* wq      = (const float*)d_in[1];
    const float* wk      = (const float*)d_in[2];
    const float* wv      = (const float*)d_in[3];
    const float* wo      = (const float*)d_in[4];
    const float* q_normw = (const float*)d_in[5];
    const float* k_normw = (const float*)d_in[6];
    float* out = (float*)d_out;

    float *Q, *K, *V, *O;
    cudaGetSymbolAddress((void**)&Q, g_Q);
    cudaGetSymbolAddress((void**)&K, g_K);
    cudaGetSymbolAddress((void**)&V, g_V);
    cudaGetSymbolAddress((void**)&O, g_O);

    const int M = B_ * T_;   // 4096

    // QKV projections (tf32 tensor cores)
    gemm_tf32<<<dim3(DM_ / 128, M / 128), 256>>>(x, wq, Q, M, H_ * DK_,   DM_);
    gemm_tf32<<<dim3((HKV_ * DK_) / 128, M / 128), 256>>>(x, wk, K, M, HKV_ * DK_, DM_);
    gemm_tf32<<<dim3((HKV_ * DK_) / 128, M / 128), 256>>>(x, wv, V, M, HKV_ * DK_, DM_);

    // RMSNorm + RoPE on Q and K (in place)
    {
        int qrows = B_ * T_ * H_;
        int krows = B_ * T_ * HKV_;
        rmsnorm_rope<<<qrows / 4, 128>>>(Q, q_normw, H_);
        rmsnorm_rope<<<krows / 4, 128>>>(K, k_normw, HKV_);
    }

    // TF32 tensor-core flash attention
    {
        int smem = SM_WORDS * (int)sizeof(unsigned);   // 102400 B
        cudaFuncSetAttribute(flash_attn_tc, cudaFuncAttributeMaxDynamicSharedMemorySize, smem);
        flash_attn_tc<<<dim3(T_ / FBM, H_, B_), 256, smem>>>();
    }

    // Output projection (tf32 tensor cores)
    gemm_tf32<<<dim3(DM_ / 128, M / 128), 256>>>(O, wo, out, M, DM_, DM_);
}

// round 6
// speedup vs baseline: 2.9702x; 1.0799x over previous
#include <cuda_runtime.h>
#include <math.h>
#include <float.h>

// Problem constants
#define B_    2
#define T_    2048
#define DM_   2048
#define H_    16
#define HKV_  4
#define DK_   128
#define GRP_  (H_/HKV_)

// Scratch (static device globals; no allocation allowed)
__device__ float g_Q[(size_t)B_*T_*H_*DK_];     // [B,T,H,DK]
__device__ float g_K[(size_t)B_*T_*HKV_*DK_];
__device__ float g_V[(size_t)B_*T_*HKV_*DK_];
__device__ float g_O[(size_t)B_*T_*H_*DK_];
// tf32-pre-rounded copies (fp32 bit layout, low mantissa zeroed, rna-rounded)
__device__ float g_Xc[(size_t)B_*T_*DM_];
__device__ float g_Wqc[(size_t)H_*DK_*DM_];
__device__ float g_Wkc[(size_t)HKV_*DK_*DM_];
__device__ float g_Wvc[(size_t)HKV_*DK_*DM_];
__device__ float g_Woc[(size_t)DM_*DM_];

__device__ __forceinline__ unsigned f2tf32(float x) {
    unsigned r;
    asm("cvt.rna.tf32.f32 %0, %1;" : "=r"(r) : "f"(x));
    return r;
}
__device__ __forceinline__ float roundtf(float x) {
    return __uint_as_float(f2tf32(x));
}

__device__ __forceinline__ void mma_tf32(float* c, const unsigned* a, const unsigned* b) {
    asm volatile(
        "mma.sync.aligned.m16n8k8.row.col.f32.tf32.tf32.f32 "
        "{%0,%1,%2,%3}, {%4,%5,%6,%7}, {%8,%9}, {%0,%1,%2,%3};\n"
        : "+f"(c[0]), "+f"(c[1]), "+f"(c[2]), "+f"(c[3])
        : "r"(a[0]), "r"(a[1]), "r"(a[2]), "r"(a[3]), "r"(b[0]), "r"(b[1]));
}

__device__ __forceinline__ void cp16(unsigned dst, const void* src) {
    asm volatile("cp.async.ca.shared.global [%0], [%1], 16;\n" :: "r"(dst), "l"(src));
}
__device__ __forceinline__ void cp_commit() {
    asm volatile("cp.async.commit_group;\n" ::: "memory");
}
template<int N> __device__ __forceinline__ void cp_wait() {
    asm volatile("cp.async.wait_group %0;\n" :: "n"(N) : "memory");
}

// ---------------------------------------------------------------------------
// Pre-round a buffer to tf32 bits (rna). n4 = n/4.
// ---------------------------------------------------------------------------
__global__ void round_tf32_kernel(const float* __restrict__ in,
                                  float* __restrict__ out, int n4)
{
    int i = blockIdx.x * blockDim.x + threadIdx.x;
    if (i < n4) {
        float4 v = ((const float4*)in)[i];
        ((uint4*)out)[i] = make_uint4(f2tf32(v.x), f2tf32(v.y),
                                      f2tf32(v.z), f2tf32(v.w));
    }
}

// ---------------------------------------------------------------------------
// TF32 GEMM v2: 3-stage cp.async pipeline, inputs pre-rounded to tf32 bits.
// C[m,n] = sum_k A[m,k]*W[n,k]. 128x128 tile, BK=16, 8 warps, warp 64x32.
// ---------------------------------------------------------------------------
#define GSTG 3
#define SPAD 20

__global__ __launch_bounds__(256) void gemm_tf32(
    const float* __restrict__ A, const float* __restrict__ W,
    float* __restrict__ C, int M, int N, int K, int round_out)
{
    extern __shared__ unsigned gsm[];
    unsigned* As = gsm;                         // [GSTG][128*SPAD]
    unsigned* Bs = gsm + GSTG * 128 * SPAD;

    const int tid  = threadIdx.x;
    const int lane = tid & 31;
    const int warp = tid >> 5;
    const int wm   = warp >> 2;
    const int wn   = warp & 3;
    const int row0 = blockIdx.y * 128;
    const int col0 = blockIdx.x * 128;
    const int lrow = tid >> 1;
    const int lk   = (tid & 1) * 8;
    const float* Ag = A + (size_t)(row0 + lrow) * K + lk;
    const float* Wg = W + (size_t)(col0 + lrow) * K + lk;
    const int g4 = lane >> 2;
    const int q4 = lane & 3;

    const unsigned sA = (unsigned)__cvta_generic_to_shared(As);
    const unsigned sB = (unsigned)__cvta_generic_to_shared(Bs);

#define G_ISSUE(s, k0) do {                                            \
        unsigned da = sA + (unsigned)(((s) * 128 * SPAD + lrow * SPAD + lk) * 4); \
        cp16(da,      Ag + (k0));                                      \
        cp16(da + 16, Ag + (k0) + 4);                                  \
        unsigned db = sB + (unsigned)(((s) * 128 * SPAD + lrow * SPAD + lk) * 4); \
        cp16(db,      Wg + (k0));                                      \
        cp16(db + 16, Wg + (k0) + 4);                                  \
    } while (0)

    float acc[4][4][4];
#pragma unroll
    for (int i = 0; i < 4; i++)
#pragma unroll
        for (int j = 0; j < 4; j++)
#pragma unroll
            for (int r = 0; r < 4; r++) acc[i][j][r] = 0.f;

    G_ISSUE(0, 0);  cp_commit();
    G_ISSUE(1, 16); cp_commit();

    const int niter = K / 16;
    int rd = 0, wr = 2;
    for (int it = 0; it < niter; it++) {
        cp_wait<1>();
        __syncthreads();
        if (it + 2 < niter) G_ISSUE(wr, (it + 2) * 16);
        cp_commit();

        const unsigned* Asr = As + rd * 128 * SPAD;
        const unsigned* Bsr = Bs + rd * 128 * SPAD;
#pragma unroll
        for (int kk = 0; kk < 2; kk++) {
            const int kb = kk * 8;
            unsigned af[4][4];
#pragma unroll
            for (int ma = 0; ma < 4; ma++) {
                int r = wm * 64 + ma * 16 + g4;
                af[ma][0] = Asr[(r    ) * SPAD + kb + q4];
                af[ma][1] = Asr[(r + 8) * SPAD + kb + q4];
                af[ma][2] = Asr[(r    ) * SPAD + kb + 4 + q4];
                af[ma][3] = Asr[(r + 8) * SPAD + kb + 4 + q4];
            }
            unsigned bf[4][2];
#pragma unroll
            for (int na = 0; na < 4; na++) {
                int c = wn * 32 + na * 8 + g4;
                bf[na][0] = Bsr[c * SPAD + kb + q4];
                bf[na][1] = Bsr[c * SPAD + kb + 4 + q4];
            }
#pragma unroll
            for (int ma = 0; ma < 4; ma++)
#pragma unroll
                for (int na = 0; na < 4; na++)
                    mma_tf32(acc[ma][na], af[ma], bf[na]);
        }
        rd = (rd + 1 == GSTG) ? 0 : rd + 1;
        wr = (wr + 1 == GSTG) ? 0 : wr + 1;
    }

#pragma unroll
    for (int ma = 0; ma < 4; ma++) {
#pragma unroll
        for (int na = 0; na < 4; na++) {
            int r = row0 + wm * 64 + ma * 16 + g4;
            int c = col0 + wn * 32 + na * 8 + 2 * q4;
            float v0 = acc[ma][na][0], v1 = acc[ma][na][1];
            float v2 = acc[ma][na][2], v3 = acc[ma][na][3];
            if (round_out) {
                v0 = roundtf(v0); v1 = roundtf(v1);
                v2 = roundtf(v2); v3 = roundtf(v3);
            }
            *(float2*)(C + (size_t)r * N + c) = make_float2(v0, v1);
            *(float2*)(C + (size_t)(r + 8) * N + c) = make_float2(v2, v3);
        }
    }
}

// ---------------------------------------------------------------------------
// Fused RMSNorm + RoPE, in place; outputs tf32-rounded bits.
// ---------------------------------------------------------------------------
__global__ void rmsnorm_rope(float* __restrict__ X, const float* __restrict__ w,
                             int nheads)
{
    int gwarp = (blockIdx.x * blockDim.x + threadIdx.x) >> 5;
    int lane  = threadIdx.x & 31;
    int total = B_ * T_ * nheads;
    if (gwarp >= total) return;

    int t = (gwarp / nheads) % T_;
    float* row = X + (size_t)gwarp * DK_;

    float4 v = *(float4*)(row + lane * 4);
    float ss = v.x * v.x + v.y * v.y + v.z * v.z + v.w * v.w;
#pragma unroll
    for (int o = 16; o; o >>= 1) ss += __shfl_xor_sync(0xffffffffu, ss, o);

    float scale = rsqrtf(ss * (1.0f / DK_) + 1.1920929e-7f);

    float4 wv = *(const float4*)(w + lane * 4);
    float x0 = v.x * scale * wv.x;
    float x1 = v.y * scale * wv.y;
    float x2 = v.z * scale * wv.z;
    float x3 = v.w * scale * wv.w;

    int p0 = lane * 2, p1 = lane * 2 + 1;
    float f0 = powf(10000.0f, -(float)p0 / 64.0f);
    float f1 = powf(10000.0f, -(float)p1 / 64.0f);
    float tf = (float)t;
    float s0, c0, s1, c1;
    sincosf(tf * f0, &s0, &c0);
    sincosf(tf * f1, &s1, &c1);

    float4 out;
    out.x = roundtf(x0 * c0 - x1 * s0);
    out.y = roundtf(x1 * c0 + x0 * s0);
    out.z = roundtf(x2 * c1 - x3 * s1);
    out.w = roundtf(x3 * c1 + x2 * s1);
    *(float4*)(row + lane * 4) = out;
}

// ---------------------------------------------------------------------------
// TF32 tensor-core flash attention v2: cp.async double-buffered K/V staging.
// Inputs (g_Q, g_K, g_V) already tf32-rounded. Output tf32-rounded.
// FIXED vs round 5: staging covers the FULL 128-float row (32 x 16B chunks),
// 16 cp16 per thread per tile instead of 4.
// ---------------------------------------------------------------------------
#define FBM 128
#define FBN 64
#define KVS 132
#define PST 68
#define SKV (2 * 64 * KVS)          // one stage: K tile + V tile (words)
#define SM_P (2 * SKV)
#define SM_WORDS (SM_P + 8 * 16 * PST)

__global__ __launch_bounds__(256, 1) void flash_attn_tc()
{
    extern __shared__ unsigned smu[];

    const int qtile = (gridDim.x - 1) - blockIdx.x;   // heavy tiles first
    const int h     = blockIdx.y;
    const int b     = blockIdx.z;
    const int hkv   = h / GRP_;

    const int tid  = threadIdx.x;
    const int lane = tid & 31;
    const int warp = tid >> 5;
    const int g4   = lane >> 2;
    const int q4   = lane & 3;

    const int qrow0 = qtile * FBM;
    const int rA    = qrow0 + warp * 16 + g4;
    const int rB    = rA + 8;
    const int wrmax = qrow0 + warp * 16 + 15;

    const unsigned smem_base = (unsigned)__cvta_generic_to_shared(smu);
    unsigned* Ps = smu + SM_P + warp * (16 * PST);

    // ---- prologue: cp.async Q tile (128 rows x 128 floats = 4096 x 16B) ----
    {
        const float* Qbase = g_Q + (((size_t)(b * T_ + qrow0) * H_ + h) * DK_);
#pragma unroll
        for (int i = 0; i < 16; i++) {
            int c  = tid + 256 * i;          // 0..4095
            int r  = c >> 5;                 // 0..127
            int cc = c & 31;                 // float4 index within row
            cp16(smem_base + (unsigned)((r * KVS + cc * 4) * 4),
                 Qbase + (size_t)r * (H_ * DK_) + cc * 4);
        }
        cp_commit();
        cp_wait<0>();
        __syncthreads();
    }

    unsigned qf[16][4];
#pragma unroll
    for (int kat = 0; kat < 16; kat++) {
        int kb = kat * 8;
        int r0 = warp * 16 + g4;
        qf[kat][0] = smu[(r0    ) * KVS + kb + q4];
        qf[kat][1] = smu[(r0 + 8) * KVS + kb + q4];
        qf[kat][2] = smu[(r0    ) * KVS + kb + 4 + q4];
        qf[kat][3] = smu[(r0 + 8) * KVS + kb + 4 + q4];
    }
    __syncthreads();   // all frags extracted before K/V overwrites the region

    const size_t kvrow = (size_t)HKV_ * DK_;
    const float* Kb = g_K + (((size_t)b * T_ * HKV_ + hkv) * DK_);
    const float* Vb = g_V + (((size_t)b * T_ * HKV_ + hkv) * DK_);

// K tile: 64 rows x 32 chunks = 2048; V same => 4096 cp16 = 16 per thread.
#define KV_ISSUE(stg, kt) do {                                               \
        int kb0 = (kt) * FBN;                                                \
        unsigned sb = smem_base + (unsigned)((stg) * SKV * 4);               \
        _Pragma("unroll")                                                    \
        for (int i = 0; i < 16; i++) {                                       \
            int c  = tid + 256 * i;        /* 0..4095 */                     \
            int tn = c >> 11;              /* 0=K, 1=V */                    \
            int r  = (c >> 5) & 63;                                          \
            int cc = c & 31;                                                 \
            const float* src = (tn ? Vb : Kb) + (size_t)(kb0 + r) * kvrow + cc * 4; \
            cp16(sb + (unsigned)(((tn * 64 + r) * KVS + cc * 4) * 4), src);  \
        }                                                                    \
    } while (0)

    float oacc[16][4];
#pragma unroll
    for (int i = 0; i < 16; i++)
#pragma unroll
        for (int j = 0; j < 4; j++) oacc[i][j] = 0.f;
    float m0 = -1e30f, m1 = -1e30f, l0 = 0.f, l1 = 0.f;
    const float sc = 0.08838834764831845f;

    const int nchunks = (qtile + 1) * (FBM / FBN);

    KV_ISSUE(0, 0); cp_commit();

    for (int kt = 0; kt < nchunks; kt++) {
        cp_wait<0>();
        __syncthreads();
        if (kt + 1 < nchunks) KV_ISSUE((kt + 1) & 1, kt + 1);
        cp_commit();

        const int kbase = kt * FBN;
        unsigned* Ks = smu + (kt & 1) * SKV;
        unsigned* Vs = Ks + 64 * KVS;

        if (kbase <= wrmax) {
            // ---- S = Q K^T ----
            float sacc[8][4];
#pragma unroll
            for (int n = 0; n < 8; n++)
#pragma unroll
                for (int j = 0; j < 4; j++) sacc[n][j] = 0.f;

#pragma unroll
            for (int kat = 0; kat < 16; kat++) {
                int kb = kat * 8;
#pragma unroll
                for (int nat = 0; nat < 8; nat++) {
                    unsigned bb[2];
                    bb[0] = Ks[(nat * 8 + g4) * KVS + kb + q4];
                    bb[1] = Ks[(nat * 8 + g4) * KVS + kb + 4 + q4];
                    mma_tf32(sacc[nat], qf[kat], bb);
                }
            }

            // ---- scale + causal mask ----
            const bool needmask = (kbase + FBN - 1 > rA);
#pragma unroll
            for (int nat = 0; nat < 8; nat++) {
                int c0 = kbase + nat * 8 + 2 * q4;
                sacc[nat][0] *= sc; sacc[nat][1] *= sc;
                sacc[nat][2] *= sc; sacc[nat][3] *= sc;
                if (needmask) {
                    if (c0     > rA) sacc[nat][0] = -1e30f;
                    if (c0 + 1 > rA) sacc[nat][1] = -1e30f;
                    if (c0     > rB) sacc[nat][2] = -1e30f;
                    if (c0 + 1 > rB) sacc[nat][3] = -1e30f;
                }
            }

            // ---- online softmax (warp-local) ----
            float mA = -1e30f, mB = -1e30f;
#pragma unroll
            for (int nat = 0; nat < 8; nat++) {
                mA = fmaxf(mA, fmaxf(sacc[nat][0], sacc[nat][1]));
                mB = fmaxf(mB, fmaxf(sacc[nat][2], sacc[nat][3]));
            }
            mA = fmaxf(mA, __shfl_xor_sync(0xffffffffu, mA, 1));
            mA = fmaxf(mA, __shfl_xor_sync(0xffffffffu, mA, 2));
            mB = fmaxf(mB, __shfl_xor_sync(0xffffffffu, mB, 1));
            mB = fmaxf(mB, __shfl_xor_sync(0xffffffffu, mB, 2));

            float nm0 = fmaxf(m0, mA), nm1 = fmaxf(m1, mB);
            float corr0 = __expf(m0 - nm0);
            float corr1 = __expf(m1 - nm1);
            float ps0 = 0.f, ps1 = 0.f;
#pragma unroll
            for (int nat = 0; nat < 8; nat++) {
                sacc[nat][0] = __expf(sacc[nat][0] - nm0);
                sacc[nat][1] = __expf(sacc[nat][1] - nm0);
                sacc[nat][2] = __expf(sacc[nat][2] - nm1);
                sacc[nat][3] = __expf(sacc[nat][3] - nm1);
                ps0 += sacc[nat][0] + sacc[nat][1];
                ps1 += sacc[nat][2] + sacc[nat][3];
            }
            ps0 += __shfl_xor_sync(0xffffffffu, ps0, 1);
            ps0 += __shfl_xor_sync(0xffffffffu, ps0, 2);
            ps1 += __shfl_xor_sync(0xffffffffu, ps1, 1);
            ps1 += __shfl_xor_sync(0xffffffffu, ps1, 2);
            l0 = l0 * corr0 + ps0;
            l1 = l1 * corr1 + ps1;
            m0 = nm0; m1 = nm1;

#pragma unroll
            for (int nv = 0; nv < 16; nv++) {
                oacc[nv][0] *= corr0; oacc[nv][1] *= corr0;
                oacc[nv][2] *= corr1; oacc[nv][3] *= corr1;
            }

            // ---- stash P (tf32) into per-warp smem tile ----
#pragma unroll
            for (int nat = 0; nat < 8; nat++) {
                int cc = nat * 8 + 2 * q4;
                *(uint2*)(Ps + g4 * PST + cc) =
                    make_uint2(f2tf32(sacc[nat][0]), f2tf32(sacc[nat][1]));
                *(uint2*)(Ps + (g4 + 8) * PST + cc) =
                    make_uint2(f2tf32(sacc[nat][2]), f2tf32(sacc[nat][3]));
            }
            __syncwarp();

            // ---- O += P V ----
#pragma unroll
            for (int kat = 0; kat < 8; kat++) {
                int kb = kat * 8;
                unsigned af[4];
                af[0] = Ps[(g4    ) * PST + kb + q4];
                af[1] = Ps[(g4 + 8) * PST + kb + q4];
                af[2] = Ps[(g4    ) * PST + kb + 4 + q4];
                af[3] = Ps[(g4 + 8) * PST + kb + 4 + q4];
#pragma unroll
                for (int nv = 0; nv < 16; nv++) {
                    unsigned bb[2];
                    bb[0] = Vs[(kb + q4    ) * KVS + nv * 8 + g4];
                    bb[1] = Vs[(kb + q4 + 4) * KVS + nv * 8 + g4];
                    mma_tf32(oacc[nv], af, bb);
                }
            }
            __syncwarp();
        }
    }

    // ---- epilogue (tf32-rounded: O feeds the cp.async O-proj GEMM) ----
    float inv0 = 1.f / l0, inv1 = 1.f / l1;
    float* OA = g_O + (((size_t)(b * T_ + rA) * H_ + h) * DK_);
    float* OB = g_O + (((size_t)(b * T_ + rB) * H_ + h) * DK_);
#pragma unroll
    for (int nv = 0; nv < 16; nv++) {
        int cc = nv * 8 + 2 * q4;
        *(float2*)(OA + cc) = make_float2(roundtf(oacc[nv][0] * inv0),
                                          roundtf(oacc[nv][1] * inv0));
        *(float2*)(OB + cc) = make_float2(roundtf(oacc[nv][2] * inv1),
                                          roundtf(oacc[nv][3] * inv1));
    }
}

// ---------------------------------------------------------------------------
// Launch
// ---------------------------------------------------------------------------
extern "C" void kernel_launch(void* const* d_in, const int* in_sizes, int n_in,
                              void* d_out, int out_size)
{
    const float* x       = (const float*)d_in[0];
    const float* wq      = (const float*)d_in[1];
    const float* wk      = (const float*)d_in[2];
    const float* wv      = (const float*)d_in[3];
    const float* wo      = (const float*)d_in[4];
    const float* q_normw = (const float*)d_in[5];
    const float* k_normw = (const float*)d_in[6];
    float* out = (float*)d_out;

    float *Q, *K, *V, *O, *Xc, *Wqc, *Wkc, *Wvc, *Woc;
    cudaGetSymbolAddress((void**)&Q, g_Q);
    cudaGetSymbolAddress((void**)&K, g_K);
    cudaGetSymbolAddress((void**)&V, g_V);
    cudaGetSymbolAddress((void**)&O, g_O);
    cudaGetSymbolAddress((void**)&Xc, g_Xc);
    cudaGetSymbolAddress((void**)&Wqc, g_Wqc);
    cudaGetSymbolAddress((void**)&Wkc, g_Wkc);
    cudaGetSymbolAddress((void**)&Wvc, g_Wvc);
    cudaGetSymbolAddress((void**)&Woc, g_Woc);

    const int M = B_ * T_;   // 4096

    // Pre-round inputs to tf32 bits
    {
        int nx = M * DM_ / 4;
        round_tf32_kernel<<<(nx + 255) / 256, 256>>>(x, Xc, nx);
        int nq = H_ * DK_ * DM_ / 4;
        round_tf32_kernel<<<(nq + 255) / 256, 256>>>(wq, Wqc, nq);
        int nk = HKV_ * DK_ * DM_ / 4;
        round_tf32_kernel<<<(nk + 255) / 256, 256>>>(wk, Wkc, nk);
        round_tf32_kernel<<<(nk + 255) / 256, 256>>>(wv, Wvc, nk);
        round_tf32_kernel<<<(nq + 255) / 256, 256>>>(wo, Woc, nq);
    }

    int gsmem = GSTG * 128 * SPAD * 2 * (int)sizeof(unsigned);   // ~61.4 KB
    cudaFuncSetAttribute(gemm_tf32, cudaFuncAttributeMaxDynamicSharedMemorySize, gsmem);

    // QKV projections (V output pre-rounded for attention staging)
    gemm_tf32<<<dim3(DM_ / 128, M / 128), 256, gsmem>>>(Xc, Wqc, Q, M, H_ * DK_,   DM_, 0);
    gemm_tf32<<<dim3((HKV_ * DK_) / 128, M / 128), 256, gsmem>>>(Xc, Wkc, K, M, HKV_ * DK_, DM_, 0);
    gemm_tf32<<<dim3((HKV_ * DK_) / 128, M / 128), 256, gsmem>>>(Xc, Wvc, V, M, HKV_ * DK_, DM_, 1);

    // RMSNorm + RoPE on Q and K (outputs tf32-rounded)
    {
        int qrows = B_ * T_ * H_;
        int krows = B_ * T_ * HKV_;
        rmsnorm_rope<<<qrows / 4, 128>>>(Q, q_normw, H_);
        rmsnorm_rope<<<krows / 4, 128>>>(K, k_normw, HKV_);
    }

    // TF32 tensor-core flash attention (cp.async K/V pipeline)
    {
        int smem = SM_WORDS * (int)sizeof(unsigned);   // ~166 KB
        cudaFuncSetAttribute(flash_attn_tc, cudaFuncAttributeMaxDynamicSharedMemorySize, smem);
        flash_attn_tc<<<dim3(T_ / FBM, H_, B_), 256, smem>>>();
    }

    // Output projection
    gemm_tf32<<<dim3(DM_ / 128, M / 128), 256, gsmem>>>(O, Woc, out, M, DM_, DM_, 0);
}